// round 15
// baseline (speedup 1.0000x reference)
#include <cuda_runtime.h>
#include <cuda_fp16.h>
#include <cuda_bf16.h>
#include <cstdint>
#include <math.h>

#define D      128
#define N_MAX  20000
#define E_MAX  640000

// ---------------- device scratch ----------------
__device__ float g_recv[(size_t)N_MAX * D];
__device__ float g_P1[(size_t)N_MAX * D];
__device__ float g_P2[(size_t)N_MAX * D];
__device__ float g_P3[(size_t)N_MAX * D];
__device__ float g_P4[(size_t)N_MAX * D];
__device__ uint2 g_Bh[2 * 8 * 16 * 32];
__device__ uint2 g_Bl[2 * 8 * 16 * 32];
__device__ uint2 g_Bf[8 * 16 * 32];
__device__ uint2 g_Bgh[4 * 16 * 16 * 32];
__device__ uint2 g_Bgl[4 * 16 * 16 * 32];
__device__ int   g_count[N_MAX];
__device__ int   g_off[N_MAX + 1];
__device__ int   g_cursor[N_MAX];
__device__ int   g_elist[E_MAX];

__device__ __forceinline__ uint32_t pack_bf2(float a, float b) {
    __nv_bfloat162 h = __floats2bfloat162_rn(a, b);
    return *(uint32_t*)&h;
}
__device__ __forceinline__ uint32_t pack_h2(float a, float b) {
    __half2 h = __floats2half2_rn(a, b);
    return *(uint32_t*)&h;
}

#define MMA_BF16(d, a0, a1, a2, a3, b0, b1)                                    \
    asm volatile("mma.sync.aligned.m16n8k16.row.col.f32.bf16.bf16.f32 "        \
                 "{%0,%1,%2,%3}, {%4,%5,%6,%7}, {%8,%9}, {%0,%1,%2,%3};"       \
                 : "+f"((d)[0]), "+f"((d)[1]), "+f"((d)[2]), "+f"((d)[3])      \
                 : "r"(a0), "r"(a1), "r"(a2), "r"(a3), "r"(b0), "r"(b1))
#define MMA_F16(d, a0, a1, a2, a3, b0, b1)                                     \
    asm volatile("mma.sync.aligned.m16n8k16.row.col.f32.f16.f16.f32 "          \
                 "{%0,%1,%2,%3}, {%4,%5,%6,%7}, {%8,%9}, {%0,%1,%2,%3};"       \
                 : "+f"((d)[0]), "+f"((d)[1]), "+f"((d)[2]), "+f"((d)[3])      \
                 : "r"(a0), "r"(a1), "r"(a2), "r"(a3), "r"(b0), "r"(b1))

// ---------------- smem layouts ----------------
#define A_PITCH 272

// node_proj (bf16 3-term): A only in smem; B direct from global
#define NP_AH   0
#define NP_AL   (256 * A_PITCH)
#define NP_TOTAL (2 * 256 * A_PITCH)

// edge: persistent, 128-edge tiles, B staged once, A dbl-buffered.
// The consumed A buffer pair (69632B) doubles as the epilogue scratch
// (128 rows x 544B pitch = 69632B exactly).
#define EG_B    0
#define EG_ASZ  (128 * A_PITCH)
#define EG_BUF(b) (32768 + (b) * 2 * EG_ASZ)     // base of buffer pair b
#define EG_TOTAL (32768 + 4 * EG_ASZ)            // 172,032 B
#define SCR_PITCH 544

// gru (bf16 3-term): A only in smem; B direct from global
#define G_PITCH 528
#define GR_AH   0
#define GR_AL   (128 * G_PITCH)
#define GR_TOTAL (2 * 128 * G_PITCH)

// ---- staging ----
__device__ __forceinline__ void stage_A64_bf(char* awh, char* awl, const float* src) {
    #pragma unroll
    for (int q = 0; q < 8; ++q) {
        float4 v0 = __ldg((const float4*)(src + q * 8));
        float4 v1 = __ldg((const float4*)(src + q * 8 + 4));
        float h0 = __bfloat162float(__float2bfloat16_rn(v0.x));
        float h1 = __bfloat162float(__float2bfloat16_rn(v0.y));
        float h2 = __bfloat162float(__float2bfloat16_rn(v0.z));
        float h3 = __bfloat162float(__float2bfloat16_rn(v0.w));
        float h4 = __bfloat162float(__float2bfloat16_rn(v1.x));
        float h5 = __bfloat162float(__float2bfloat16_rn(v1.y));
        float h6 = __bfloat162float(__float2bfloat16_rn(v1.z));
        float h7 = __bfloat162float(__float2bfloat16_rn(v1.w));
        *(uint4*)(awh + q * 16) = make_uint4(pack_bf2(h0, h1), pack_bf2(h2, h3),
                                             pack_bf2(h4, h5), pack_bf2(h6, h7));
        *(uint4*)(awl + q * 16) = make_uint4(pack_bf2(v0.x - h0, v0.y - h1),
                                             pack_bf2(v0.z - h2, v0.w - h3),
                                             pack_bf2(v1.x - h4, v1.y - h5),
                                             pack_bf2(v1.z - h6, v1.w - h7));
    }
}

__device__ __forceinline__ void ldg_A32(float4* v, const float* src) {
    #pragma unroll
    for (int q = 0; q < 8; ++q) v[q] = __ldg((const float4*)(src + q * 4));
}
__device__ __forceinline__ void cvt_sts_A32_fp(char* awh, char* awl, const float4* v) {
    #pragma unroll
    for (int q = 0; q < 4; ++q) {
        float4 v0 = v[q * 2], v1 = v[q * 2 + 1];
        float h0 = __half2float(__float2half_rn(v0.x));
        float h1 = __half2float(__float2half_rn(v0.y));
        float h2 = __half2float(__float2half_rn(v0.z));
        float h3 = __half2float(__float2half_rn(v0.w));
        float h4 = __half2float(__float2half_rn(v1.x));
        float h5 = __half2float(__float2half_rn(v1.y));
        float h6 = __half2float(__float2half_rn(v1.z));
        float h7 = __half2float(__float2half_rn(v1.w));
        *(uint4*)(awh + q * 16) = make_uint4(pack_h2(h0, h1), pack_h2(h2, h3),
                                             pack_h2(h4, h5), pack_h2(h6, h7));
        *(uint4*)(awl + q * 16) = make_uint4(pack_h2(v0.x - h0, v0.y - h1),
                                             pack_h2(v0.z - h2, v0.w - h3),
                                             pack_h2(v1.x - h4, v1.y - h5),
                                             pack_h2(v1.z - h6, v1.w - h7));
    }
}

__device__ __forceinline__ void stage_B_eg(char* sm, int t) {
    const uint4* gb = (const uint4*)g_Bf;
    #pragma unroll
    for (int q = 0; q < 4; ++q) {
        int i = t + q * 512;
        *(uint4*)(sm + EG_B + i * 16) = __ldg(&gb[i]);
    }
}

// 16x128 warp tile, bf16 3-term; B direct from global
__device__ __forceinline__ void mma_rows16_g(char* sm, int c, int warp, int lane,
                                             float acc[16][4]) {
    char* aHip = sm + NP_AH + (warp * 16 + (lane >> 2)) * A_PITCH + (lane & 3) * 4;
    char* aLip = sm + NP_AL + (warp * 16 + (lane >> 2)) * A_PITCH + (lane & 3) * 4;
    const uint2* bhB = g_Bh + ((size_t)c * 8 * 16) * 32 + lane;
    const uint2* blB = g_Bl + ((size_t)c * 8 * 16) * 32 + lane;
    #pragma unroll
    for (int s = 0; s < 8; ++s) {
        uint32_t ah0 = *(const uint32_t*)(aHip + s * 32);
        uint32_t ah1 = *(const uint32_t*)(aHip + s * 32 + 8 * A_PITCH);
        uint32_t ah2 = *(const uint32_t*)(aHip + s * 32 + 16);
        uint32_t ah3 = *(const uint32_t*)(aHip + s * 32 + 8 * A_PITCH + 16);
        uint32_t al0 = *(const uint32_t*)(aLip + s * 32);
        uint32_t al1 = *(const uint32_t*)(aLip + s * 32 + 8 * A_PITCH);
        uint32_t al2 = *(const uint32_t*)(aLip + s * 32 + 16);
        uint32_t al3 = *(const uint32_t*)(aLip + s * 32 + 8 * A_PITCH + 16);
        #pragma unroll
        for (int j = 0; j < 16; ++j) {
            uint2 bh = __ldg(&bhB[(s * 16 + j) * 32]);
            uint2 bl = __ldg(&blB[(s * 16 + j) * 32]);
            MMA_BF16(acc[j], ah0, ah1, ah2, ah3, bh.x, bh.y);
            MMA_BF16(acc[j], ah0, ah1, ah2, ah3, bl.x, bl.y);
            MMA_BF16(acc[j], al0, al1, al2, al3, bh.x, bh.y);
        }
    }
}

// 32x64 warp tile, bf16 3-term (gru); B direct from global
__device__ __forceinline__ void mma_tile32x64_bfg(char* sm, int c, int kh,
                                                  int rg, int cg, int lane,
                                                  float acc[2][8][4]) {
    char* aHb = sm + GR_AH + (uint32_t)kh * 256 + (rg * 32 + (lane >> 2)) * G_PITCH + (lane & 3) * 4;
    char* aLb = sm + GR_AL + (uint32_t)kh * 256 + (rg * 32 + (lane >> 2)) * G_PITCH + (lane & 3) * 4;
    const uint2* bhB = g_Bgh + ((size_t)(c * 16 + kh * 8) * 16 + cg * 8) * 32 + lane;
    const uint2* blB = g_Bgl + ((size_t)(c * 16 + kh * 8) * 16 + cg * 8) * 32 + lane;
    #pragma unroll
    for (int s = 0; s < 8; ++s) {
        uint2 bh[8], bl[8];
        #pragma unroll
        for (int j = 0; j < 8; ++j) {
            bh[j] = __ldg(&bhB[(s * 16 + j) * 32]);
            bl[j] = __ldg(&blB[(s * 16 + j) * 32]);
        }
        #pragma unroll
        for (int rf = 0; rf < 2; ++rf) {
            const int ao = s * 32 + rf * 16 * G_PITCH;
            uint32_t ah0 = *(const uint32_t*)(aHb + ao);
            uint32_t ah1 = *(const uint32_t*)(aHb + ao + 8 * G_PITCH);
            uint32_t ah2 = *(const uint32_t*)(aHb + ao + 16);
            uint32_t ah3 = *(const uint32_t*)(aHb + ao + 8 * G_PITCH + 16);
            uint32_t al0 = *(const uint32_t*)(aLb + ao);
            uint32_t al1 = *(const uint32_t*)(aLb + ao + 8 * G_PITCH);
            uint32_t al2 = *(const uint32_t*)(aLb + ao + 16);
            uint32_t al3 = *(const uint32_t*)(aLb + ao + 8 * G_PITCH + 16);
            #pragma unroll
            for (int j = 0; j < 8; ++j) {
                MMA_BF16(acc[rf][j], ah0, ah1, ah2, ah3, bh[j].x, bh[j].y);
                MMA_BF16(acc[rf][j], ah0, ah1, ah2, ah3, bl[j].x, bl[j].y);
                MMA_BF16(acc[rf][j], al0, al1, al2, al3, bh[j].x, bh[j].y);
            }
        }
    }
}

// 16x64 warp tile, fp16 2-term (edge)
__device__ __forceinline__ void mma_tile16x64_fp(char* sm, uint32_t aH, uint32_t aL,
                                                 int rg, int cg, int lane,
                                                 float acc[8][4]) {
    char* aHb = sm + aH + (rg * 16 + (lane >> 2)) * A_PITCH + (lane & 3) * 4;
    char* aLb = sm + aL + (rg * 16 + (lane >> 2)) * A_PITCH + (lane & 3) * 4;
    char* bb  = sm + EG_B + cg * 8 * 256 + lane * 8;
    #pragma unroll
    for (int s = 0; s < 8; ++s) {
        uint2 b[8];
        #pragma unroll
        for (int j = 0; j < 8; ++j)
            b[j] = *(const uint2*)(bb + s * 4096 + j * 256);
        const int ao = s * 32;
        uint32_t ah0 = *(const uint32_t*)(aHb + ao);
        uint32_t ah1 = *(const uint32_t*)(aHb + ao + 8 * A_PITCH);
        uint32_t ah2 = *(const uint32_t*)(aHb + ao + 16);
        uint32_t ah3 = *(const uint32_t*)(aHb + ao + 8 * A_PITCH + 16);
        uint32_t al0 = *(const uint32_t*)(aLb + ao);
        uint32_t al1 = *(const uint32_t*)(aLb + ao + 8 * A_PITCH);
        uint32_t al2 = *(const uint32_t*)(aLb + ao + 16);
        uint32_t al3 = *(const uint32_t*)(aLb + ao + 8 * A_PITCH + 16);
        #pragma unroll
        for (int j = 0; j < 8; ++j) {
            MMA_F16(acc[j], ah0, ah1, ah2, ah3, b[j].x, b[j].y);
            MMA_F16(acc[j], al0, al1, al2, al3, b[j].x, b[j].y);
        }
    }
}

// ---------------------------------------------------------------------------
__device__ __forceinline__ float gru_w(const float* Wi, const float* Wh,
                                       int c, int k, int n) {
    if (c == 0) return k < 128 ? Wi[(size_t)k * 384 + n] : Wh[(size_t)(k - 128) * 384 + n];
    if (c == 1) return k < 128 ? Wi[(size_t)k * 384 + 128 + n] : Wh[(size_t)(k - 128) * 384 + 128 + n];
    if (c == 2) return k < 128 ? Wi[(size_t)k * 384 + 256 + n] : 0.f;
    return k < 128 ? 0.f : Wh[(size_t)(k - 128) * 384 + 256 + n];
}

__global__ void prep_kernel(const float* __restrict__ W,
                            const float* __restrict__ Wi,
                            const float* __restrict__ Wh, int N_) {
    const int stride = gridDim.x * blockDim.x;
    const int tid0 = blockIdx.x * blockDim.x + threadIdx.x;
    const int TOT = 2 * 8 * 16 * 32;
    for (int i = tid0; i < TOT; i += stride) {
        int l = i & 31, j = (i >> 5) & 15, s = (i >> 9) & 7, c = i >> 12;
        int k = c * 128 + s * 16 + (l & 3) * 2;
        int n = j * 8 + (l >> 2);
        float w00 = W[(size_t)(k + 0) * D + n];
        float w01 = W[(size_t)(k + 1) * D + n];
        float w10 = W[(size_t)(k + 8) * D + n];
        float w11 = W[(size_t)(k + 9) * D + n];
        float h00 = __bfloat162float(__float2bfloat16_rn(w00));
        float h01 = __bfloat162float(__float2bfloat16_rn(w01));
        float h10 = __bfloat162float(__float2bfloat16_rn(w10));
        float h11 = __bfloat162float(__float2bfloat16_rn(w11));
        g_Bh[i] = make_uint2(pack_bf2(h00, h01), pack_bf2(h10, h11));
        g_Bl[i] = make_uint2(pack_bf2(w00 - h00, w01 - h01),
                             pack_bf2(w10 - h10, w11 - h11));
    }
    const int TOTF = 8 * 16 * 32;
    for (int i = tid0; i < TOTF; i += stride) {
        int l = i & 31, j = (i >> 5) & 15, s = (i >> 9) & 7;
        int k = 256 + s * 16 + (l & 3) * 2;
        int n = j * 8 + (l >> 2);
        g_Bf[i] = make_uint2(
            pack_h2(W[(size_t)(k + 0) * D + n], W[(size_t)(k + 1) * D + n]),
            pack_h2(W[(size_t)(k + 8) * D + n], W[(size_t)(k + 9) * D + n]));
    }
    const int TOTG = 4 * 16 * 16 * 32;
    for (int i = tid0; i < TOTG; i += stride) {
        int l = i & 31, j = (i >> 5) & 15, s = (i >> 9) & 15, c = i >> 13;
        int k = s * 16 + (l & 3) * 2;
        int n = j * 8 + (l >> 2);
        float w00 = gru_w(Wi, Wh, c, k + 0, n);
        float w01 = gru_w(Wi, Wh, c, k + 1, n);
        float w10 = gru_w(Wi, Wh, c, k + 8, n);
        float w11 = gru_w(Wi, Wh, c, k + 9, n);
        float h00 = __bfloat162float(__float2bfloat16_rn(w00));
        float h01 = __bfloat162float(__float2bfloat16_rn(w01));
        float h10 = __bfloat162float(__float2bfloat16_rn(w10));
        float h11 = __bfloat162float(__float2bfloat16_rn(w11));
        g_Bgh[i] = make_uint2(pack_bf2(h00, h01), pack_bf2(h10, h11));
        g_Bgl[i] = make_uint2(pack_bf2(w00 - h00, w01 - h01),
                              pack_bf2(w10 - h10, w11 - h11));
    }
    for (int i = tid0; i < N_; i += stride) g_count[i] = 0;
}

__global__ void hist_kernel(const int* __restrict__ rcv, int E_) {
    int i = blockIdx.x * blockDim.x + threadIdx.x;
    if (i < E_) atomicAdd(&g_count[rcv[i]], 1);
}

__global__ void scan_kernel(int N_, int E_) {
    __shared__ int wsum[32];
    __shared__ int s_carry;
    const int t = threadIdx.x;
    const int lane = t & 31, wid = t >> 5;
    if (t == 0) s_carry = 0;
    __syncthreads();
    const int rounds = (N_ + 1023) >> 10;
    for (int r = 0; r < rounds; ++r) {
        int i = r * 1024 + t;
        int v = (i < N_) ? g_count[i] : 0;
        int x = v;
        #pragma unroll
        for (int o = 1; o < 32; o <<= 1) {
            int y = __shfl_up_sync(0xFFFFFFFFu, x, o);
            if (lane >= o) x += y;
        }
        if (lane == 31) wsum[wid] = x;
        __syncthreads();
        if (wid == 0) {
            int w = wsum[lane];
            #pragma unroll
            for (int o = 1; o < 32; o <<= 1) {
                int y = __shfl_up_sync(0xFFFFFFFFu, w, o);
                if (lane >= o) w += y;
            }
            wsum[lane] = w;
        }
        __syncthreads();
        int excl = s_carry + (wid ? wsum[wid - 1] : 0) + x - v;
        if (i < N_) { g_off[i] = excl; g_cursor[i] = excl; }
        __syncthreads();
        if (t == 0) s_carry += wsum[31];
        __syncthreads();
    }
    if (t == 0) g_off[N_] = E_;
}

__global__ void scatter_kernel(const int* __restrict__ rcv, int E_) {
    int i = blockIdx.x * blockDim.x + threadIdx.x;
    if (i < E_) {
        int p = atomicAdd(&g_cursor[rcv[i]], 1);
        g_elist[p] = i;
    }
}

// ---------------------------------------------------------------------------
__global__ __launch_bounds__(512, 1) void node_proj_kernel(
    const float* __restrict__ nodes, int N_)
{
    extern __shared__ __align__(16) char sm[];
    const int t    = threadIdx.x;
    const int warp = t >> 5, lane = t & 31;
    const int n0   = blockIdx.x * 256;

    const int row = t >> 1, hf = t & 1;
    const int ng = min(n0 + row, N_ - 1);
    stage_A64_bf(sm + NP_AH + row * A_PITCH + hf * 128,
                 sm + NP_AL + row * A_PITCH + hf * 128,
                 nodes + (size_t)ng * D + hf * 64);
    __syncthreads();

    const int nr0 = n0 + warp * 16 + (lane >> 2);
    const int nr1 = nr0 + 8;
    const int cb  = (lane & 3) * 2;

    #pragma unroll
    for (int c = 0; c < 2; ++c) {
        float acc[16][4];
        #pragma unroll
        for (int j = 0; j < 16; ++j)
            #pragma unroll
            for (int q = 0; q < 4; ++q) acc[j][q] = 0.f;

        mma_rows16_g(sm, c, warp, lane, acc);

        float* P = c == 0 ? g_P1 : g_P2;
        #pragma unroll
        for (int j = 0; j < 16; ++j) {
            int col = j * 8 + cb;
            if (nr0 < N_) *(float2*)(P + (size_t)nr0 * D + col) = make_float2(acc[j][0], acc[j][1]);
            if (nr1 < N_) *(float2*)(P + (size_t)nr1 * D + col) = make_float2(acc[j][2], acc[j][3]);
        }
    }
}

// ---------------------------------------------------------------------------
// Edge (fp16 2-term): persistent, 128-edge tiles, dbl-buffered A,
// full-line epilogue via smem transpose (scratch = consumed A buffer).
__global__ __launch_bounds__(512, 1) void edge_mma_kernel(
    const float* __restrict__ edges, const float* __restrict__ bvec,
    const int* __restrict__ snd, const int* __restrict__ rcv,
    float* __restrict__ msg, int E_, int ntiles)
{
    extern __shared__ __align__(16) char sm[];
    __shared__ float s_bias[128];

    const int t    = threadIdx.x;
    const int warp = t >> 5, lane = t & 31;
    const int rg   = warp >> 1, cg = warp & 1;

    if (t < 128) s_bias[t] = bvec[t];
    stage_B_eg(sm, t);

    // A staging geometry: 4 threads/row, 32 floats each
    const int srow = t >> 2, qt = t & 3;
    const uint32_t aRow = srow * A_PITCH + qt * 64;

    int tile = blockIdx.x;
    float4 v[8];
    {
        int eg = min(tile * 128 + srow, E_ - 1);
        ldg_A32(v, edges + (size_t)eg * D + qt * 32);
        cvt_sts_A32_fp(sm + EG_BUF(0) + aRow, sm + EG_BUF(0) + EG_ASZ + aRow, v);
    }

    // mma fragment geometry
    const int rfrag = rg * 16 + (lane >> 2);         // + hb*8
    const int cbf   = cg * 64 + (lane & 3) * 2;      // + j*8

    // epilogue read geometry: 8 lanes per row, 16 floats each
    const int erow = t >> 3, seg = t & 7;            // rows erow, erow+64

    int buf = 0;
    for (; tile < ntiles; tile += gridDim.x) {
        int ntile = tile + gridDim.x;
        // prefetch next tile's A + this tile's gather indices
        if (ntile < ntiles) {
            int eg = min(ntile * 128 + srow, E_ - 1);
            ldg_A32(v, edges + (size_t)eg * D + qt * 32);
        }
        const int erA = tile * 128 + erow;
        const int erB = erA + 64;
        int snA = __ldg(&snd[min(erA, E_ - 1)]), rcA = __ldg(&rcv[min(erA, E_ - 1)]);
        int snB = __ldg(&snd[min(erB, E_ - 1)]), rcB = __ldg(&rcv[min(erB, E_ - 1)]);

        __syncthreads();   // A[buf] staged; prior-phase readers/writers done

        float acc[8][4];
        #pragma unroll
        for (int j = 0; j < 8; ++j)
            #pragma unroll
            for (int q = 0; q < 4; ++q) acc[j][q] = 0.f;

        mma_tile16x64_fp(sm, EG_BUF(buf), EG_BUF(buf) + EG_ASZ, rg, cg, lane, acc);

        // stage next tile's A into the other buffer (its readers finished
        // last iteration; ordered by the sync above)
        if (ntile < ntiles) {
            cvt_sts_A32_fp(sm + EG_BUF(buf ^ 1) + aRow,
                           sm + EG_BUF(buf ^ 1) + EG_ASZ + aRow, v);
        }

        __syncthreads();   // all mma reads of A[buf] done -> reuse as scratch

        // transpose acc into scratch (row-major, pitch 544)
        char* scr = sm + EG_BUF(buf);
        #pragma unroll
        for (int hb = 0; hb < 2; ++hb) {
            int rl = rfrag + hb * 8;
            #pragma unroll
            for (int j = 0; j < 8; ++j) {
                *(float2*)(scr + rl * SCR_PITCH + (cbf + j * 8) * 4) =
                    make_float2(acc[j][hb * 2], acc[j][hb * 2 + 1]);
            }
        }
        __syncthreads();   // scratch complete

        // full-line epilogue: 8 lanes/row, float4 gathers + stores
        #pragma unroll
        for (int half = 0; half < 2; ++half) {
            int er = half ? erB : erA;
            if (er < E_) {
                int rl = erow + half * 64;
                const float* p1 = g_P1 + (size_t)(half ? snB : snA) * D + seg * 16;
                const float* p2 = g_P2 + (size_t)(half ? rcB : rcA) * D + seg * 16;
                const char*  sr = scr + rl * SCR_PITCH + seg * 64;
                float* mp = msg + (size_t)er * D + seg * 16;
                #pragma unroll
                for (int k = 0; k < 4; ++k) {
                    float4 a  = *(const float4*)(sr + k * 16);
                    float4 q1 = __ldg((const float4*)(p1 + k * 4));
                    float4 q2 = __ldg((const float4*)(p2 + k * 4));
                    float4 bi4 = *(const float4*)&s_bias[seg * 16 + k * 4];
                    float4 o;
                    o.x = fmaxf(a.x + q1.x + q2.x + bi4.x, 0.f);
                    o.y = fmaxf(a.y + q1.y + q2.y + bi4.y, 0.f);
                    o.z = fmaxf(a.z + q1.z + q2.z + bi4.z, 0.f);
                    o.w = fmaxf(a.w + q1.w + q2.w + bi4.w, 0.f);
                    *(float4*)(mp + k * 4) = o;
                }
            }
        }
        buf ^= 1;
    }
}

// ---------------------------------------------------------------------------
__global__ __launch_bounds__(128) void aggregate_kernel(const float* __restrict__ msg, int N_) {
    const int n = blockIdx.x;
    const int t = threadIdx.x;
    const int s = g_off[n], e = g_off[n + 1];
    float a0 = 0.f, a1 = 0.f, a2 = 0.f, a3 = 0.f;
    int i = s;
    for (; i + 4 <= e; i += 4) {
        int i0 = __ldg(&g_elist[i]);
        int i1 = __ldg(&g_elist[i + 1]);
        int i2 = __ldg(&g_elist[i + 2]);
        int i3 = __ldg(&g_elist[i + 3]);
        a0 += __ldg(&msg[(size_t)i0 * D + t]);
        a1 += __ldg(&msg[(size_t)i1 * D + t]);
        a2 += __ldg(&msg[(size_t)i2 * D + t]);
        a3 += __ldg(&msg[(size_t)i3 * D + t]);
    }
    for (; i < e; ++i) a0 += __ldg(&msg[(size_t)__ldg(&g_elist[i]) * D + t]);
    g_recv[(size_t)n * D + t] = (a0 + a1) + (a2 + a3);
}

// ---------------------------------------------------------------------------
__global__ __launch_bounds__(256, 1) void gru_mma_kernel(
    const float* __restrict__ nodes, int N_)
{
    extern __shared__ __align__(16) char sm[];
    const int t    = threadIdx.x;
    const int warp = t >> 5, lane = t & 31;
    const int n0   = blockIdx.x * 128;
    const int rg   = warp >> 1, cg = warp & 1;

    {
        const int row = t >> 1, hf = t & 1;
        const int ng = min(n0 + row, N_ - 1);
        #pragma unroll
        for (int qq = 0; qq < 2; ++qq) {
            int q = hf * 2 + qq;
            const float* src = (q < 2) ? (g_recv + (size_t)ng * D + q * 64)
                                       : (nodes + (size_t)ng * D + (q - 2) * 64);
            stage_A64_bf(sm + GR_AH + row * G_PITCH + q * 128,
                         sm + GR_AL + row * G_PITCH + q * 128, src);
        }
    }
    __syncthreads();

    const int cb = cg * 64 + (lane & 3) * 2;

    #pragma unroll
    for (int c = 0; c < 4; ++c) {
        const int kh_lo = (c == 3) ? 1 : 0;
        const int kh_hi = (c == 2) ? 0 : 1;

        float acc[2][8][4];
        #pragma unroll
        for (int rf = 0; rf < 2; ++rf)
            #pragma unroll
            for (int j = 0; j < 8; ++j)
                #pragma unroll
                for (int q = 0; q < 4; ++q) acc[rf][j][q] = 0.f;

        for (int kh = kh_lo; kh <= kh_hi; ++kh)
            mma_tile32x64_bfg(sm, c, kh, rg, cg, lane, acc);

        float* P = (c == 0) ? g_P1 : (c == 1) ? g_P2 : (c == 2) ? g_P3 : g_P4;
        #pragma unroll
        for (int rf = 0; rf < 2; ++rf)
            #pragma unroll
            for (int hb = 0; hb < 2; ++hb) {
                int nr = n0 + rg * 32 + rf * 16 + (lane >> 2) + hb * 8;
                if (nr < N_) {
                    #pragma unroll
                    for (int j = 0; j < 8; ++j) {
                        int col = cb + j * 8;
                        *(float2*)(P + (size_t)nr * D + col) =
                            make_float2(acc[rf][j][hb * 2], acc[rf][j][hb * 2 + 1]);
                    }
                }
            }
    }
}

__global__ __launch_bounds__(256) void gru_elem_kernel(
    const float* __restrict__ nodes, const float* __restrict__ bi,
    const float* __restrict__ bhn, float* __restrict__ out, int total)
{
    int i = blockIdx.x * blockDim.x + threadIdx.x;
    if (i >= total) return;
    int col = i & 127;
    float pre_r = g_P1[i] + __ldg(&bi[col]);
    float pre_z = g_P2[i] + __ldg(&bi[128 + col]);
    float i_n   = g_P3[i] + __ldg(&bi[256 + col]);
    float h_n   = g_P4[i] + __ldg(&bhn[col]);
    float r = 1.f / (1.f + expf(-pre_r));
    float z = 1.f / (1.f + expf(-pre_z));
    float n = tanhf(i_n + r * h_n);
    float h = __ldg(&nodes[i]);
    out[i] = (1.f - z) * n + z * h;
}

// ---------------------------------------------------------------------------
extern "C" void kernel_launch(void* const* d_in, const int* in_sizes, int n_in,
                              void* d_out, int out_size)
{
    const float* nodes  = (const float*)d_in[0];
    const float* edges  = (const float*)d_in[1];
    const float* W_edge = (const float*)d_in[2];
    const float* b_edge = (const float*)d_in[3];
    const float* Wi     = (const float*)d_in[4];
    const float* bi     = (const float*)d_in[5];
    const float* Wh     = (const float*)d_in[6];
    const float* bh_n   = (const float*)d_in[7];
    const int*   snd    = (const int*)d_in[8];
    const int*   rcv    = (const int*)d_in[9];

    const int N_ = in_sizes[0] / D;
    const int E_ = in_sizes[8];

    float* new_nodes = (float*)d_out;
    float* messages  = (float*)d_out + (size_t)N_ * D;

    cudaFuncSetAttribute(node_proj_kernel,
                         cudaFuncAttributeMaxDynamicSharedMemorySize, NP_TOTAL);
    cudaFuncSetAttribute(edge_mma_kernel,
                         cudaFuncAttributeMaxDynamicSharedMemorySize, EG_TOTAL);
    cudaFuncSetAttribute(gru_mma_kernel,
                         cudaFuncAttributeMaxDynamicSharedMemorySize, GR_TOTAL);

    const int ntiles = (E_ + 127) / 128;
    const int egrid  = ntiles < 148 ? ntiles : 148;

    prep_kernel<<<96, 256>>>(W_edge, Wi, Wh, N_);
    node_proj_kernel<<<(N_ + 255) / 256, 512, NP_TOTAL>>>(nodes, N_);
    hist_kernel<<<(E_ + 255) / 256, 256>>>(rcv, E_);
    edge_mma_kernel<<<egrid, 512, EG_TOTAL>>>(
        edges, b_edge, snd, rcv, messages, E_, ntiles);
    scan_kernel<<<1, 1024>>>(N_, E_);
    scatter_kernel<<<(E_ + 255) / 256, 256>>>(rcv, E_);
    aggregate_kernel<<<N_, 128>>>(messages, N_);
    gru_mma_kernel<<<(N_ + 127) / 128, 256, GR_TOTAL>>>(nodes, N_);
    gru_elem_kernel<<<(N_ * D + 255) / 256, 256>>>(nodes, bi, bh_n,
                                                   new_nodes, N_ * D);
}

// round 16
// speedup vs baseline: 1.0177x; 1.0177x over previous
#include <cuda_runtime.h>
#include <cuda_fp16.h>
#include <cuda_bf16.h>
#include <cstdint>
#include <math.h>

#define D      128
#define N_MAX  20000
#define E_MAX  640000

// ---------------- device scratch ----------------
__device__ float g_recv[(size_t)N_MAX * D];
__device__ float g_P1[(size_t)N_MAX * D];
__device__ float g_P2[(size_t)N_MAX * D];
__device__ float g_P3[(size_t)N_MAX * D];
__device__ uint2 g_Bh[2 * 8 * 16 * 32];
__device__ uint2 g_Bl[2 * 8 * 16 * 32];
__device__ uint2 g_Bf[8 * 16 * 32];
__device__ uint2 g_Bgh[4 * 16 * 16 * 32];
__device__ uint2 g_Bgl[4 * 16 * 16 * 32];
__device__ int   g_count[N_MAX];
__device__ int   g_off[N_MAX + 1];
__device__ int   g_cursor[N_MAX];
__device__ int   g_elist[E_MAX];

__device__ __forceinline__ uint32_t pack_bf2(float a, float b) {
    __nv_bfloat162 h = __floats2bfloat162_rn(a, b);
    return *(uint32_t*)&h;
}
__device__ __forceinline__ uint32_t pack_h2(float a, float b) {
    __half2 h = __floats2half2_rn(a, b);
    return *(uint32_t*)&h;
}

#define MMA_BF16(d, a0, a1, a2, a3, b0, b1)                                    \
    asm volatile("mma.sync.aligned.m16n8k16.row.col.f32.bf16.bf16.f32 "        \
                 "{%0,%1,%2,%3}, {%4,%5,%6,%7}, {%8,%9}, {%0,%1,%2,%3};"       \
                 : "+f"((d)[0]), "+f"((d)[1]), "+f"((d)[2]), "+f"((d)[3])      \
                 : "r"(a0), "r"(a1), "r"(a2), "r"(a3), "r"(b0), "r"(b1))
#define MMA_F16(d, a0, a1, a2, a3, b0, b1)                                     \
    asm volatile("mma.sync.aligned.m16n8k16.row.col.f32.f16.f16.f32 "          \
                 "{%0,%1,%2,%3}, {%4,%5,%6,%7}, {%8,%9}, {%0,%1,%2,%3};"       \
                 : "+f"((d)[0]), "+f"((d)[1]), "+f"((d)[2]), "+f"((d)[3])      \
                 : "r"(a0), "r"(a1), "r"(a2), "r"(a3), "r"(b0), "r"(b1))

// ---------------- smem layouts ----------------
#define A_PITCH 272

// node_proj (bf16 3-term): A only in smem; B direct from global
#define NP_AH   0
#define NP_AL   (256 * A_PITCH)
#define NP_TOTAL (2 * 256 * A_PITCH)

// edge (fp16 SINGLE-term): persistent, 128-edge tiles, B staged once,
// A (hi only) double-buffered.
#define EG_B    0
#define EG_ASZ  (128 * A_PITCH)
#define EG_A0   32768
#define EG_A1   (32768 + EG_ASZ)
#define EG_TOTAL (32768 + 2 * EG_ASZ)            // 102,400 B

// gru (bf16 3-term): A only in smem; B direct from global
#define G_PITCH 528
#define GR_AH   0
#define GR_AL   (128 * G_PITCH)
#define GR_TOTAL (2 * 128 * G_PITCH)

// ---- staging ----
__device__ __forceinline__ void stage_A64_bf(char* awh, char* awl, const float* src) {
    #pragma unroll
    for (int q = 0; q < 8; ++q) {
        float4 v0 = __ldg((const float4*)(src + q * 8));
        float4 v1 = __ldg((const float4*)(src + q * 8 + 4));
        float h0 = __bfloat162float(__float2bfloat16_rn(v0.x));
        float h1 = __bfloat162float(__float2bfloat16_rn(v0.y));
        float h2 = __bfloat162float(__float2bfloat16_rn(v0.z));
        float h3 = __bfloat162float(__float2bfloat16_rn(v0.w));
        float h4 = __bfloat162float(__float2bfloat16_rn(v1.x));
        float h5 = __bfloat162float(__float2bfloat16_rn(v1.y));
        float h6 = __bfloat162float(__float2bfloat16_rn(v1.z));
        float h7 = __bfloat162float(__float2bfloat16_rn(v1.w));
        *(uint4*)(awh + q * 16) = make_uint4(pack_bf2(h0, h1), pack_bf2(h2, h3),
                                             pack_bf2(h4, h5), pack_bf2(h6, h7));
        *(uint4*)(awl + q * 16) = make_uint4(pack_bf2(v0.x - h0, v0.y - h1),
                                             pack_bf2(v0.z - h2, v0.w - h3),
                                             pack_bf2(v1.x - h4, v1.y - h5),
                                             pack_bf2(v1.z - h6, v1.w - h7));
    }
}

__device__ __forceinline__ void ldg_A32(float4* v, const float* src) {
    #pragma unroll
    for (int q = 0; q < 8; ++q) v[q] = __ldg((const float4*)(src + q * 4));
}
// single-term fp16: 32 floats -> 64B fp16
__device__ __forceinline__ void cvt_sts_A32_fp1(char* awh, const float4* v) {
    #pragma unroll
    for (int q = 0; q < 4; ++q) {
        float4 v0 = v[q * 2], v1 = v[q * 2 + 1];
        *(uint4*)(awh + q * 16) = make_uint4(pack_h2(v0.x, v0.y), pack_h2(v0.z, v0.w),
                                             pack_h2(v1.x, v1.y), pack_h2(v1.z, v1.w));
    }
}

__device__ __forceinline__ void stage_B_eg(char* sm, int t) {
    const uint4* gb = (const uint4*)g_Bf;
    #pragma unroll
    for (int q = 0; q < 4; ++q) {
        int i = t + q * 512;
        *(uint4*)(sm + EG_B + i * 16) = __ldg(&gb[i]);
    }
}

// 16x128 warp tile, bf16 3-term; B direct from global
__device__ __forceinline__ void mma_rows16_g(char* sm, int c, int warp, int lane,
                                             float acc[16][4]) {
    char* aHip = sm + NP_AH + (warp * 16 + (lane >> 2)) * A_PITCH + (lane & 3) * 4;
    char* aLip = sm + NP_AL + (warp * 16 + (lane >> 2)) * A_PITCH + (lane & 3) * 4;
    const uint2* bhB = g_Bh + ((size_t)c * 8 * 16) * 32 + lane;
    const uint2* blB = g_Bl + ((size_t)c * 8 * 16) * 32 + lane;
    #pragma unroll
    for (int s = 0; s < 8; ++s) {
        uint32_t ah0 = *(const uint32_t*)(aHip + s * 32);
        uint32_t ah1 = *(const uint32_t*)(aHip + s * 32 + 8 * A_PITCH);
        uint32_t ah2 = *(const uint32_t*)(aHip + s * 32 + 16);
        uint32_t ah3 = *(const uint32_t*)(aHip + s * 32 + 8 * A_PITCH + 16);
        uint32_t al0 = *(const uint32_t*)(aLip + s * 32);
        uint32_t al1 = *(const uint32_t*)(aLip + s * 32 + 8 * A_PITCH);
        uint32_t al2 = *(const uint32_t*)(aLip + s * 32 + 16);
        uint32_t al3 = *(const uint32_t*)(aLip + s * 32 + 8 * A_PITCH + 16);
        #pragma unroll
        for (int j = 0; j < 16; ++j) {
            uint2 bh = __ldg(&bhB[(s * 16 + j) * 32]);
            uint2 bl = __ldg(&blB[(s * 16 + j) * 32]);
            MMA_BF16(acc[j], ah0, ah1, ah2, ah3, bh.x, bh.y);
            MMA_BF16(acc[j], ah0, ah1, ah2, ah3, bl.x, bl.y);
            MMA_BF16(acc[j], al0, al1, al2, al3, bh.x, bh.y);
        }
    }
}

// 32x64 warp tile, bf16 3-term (gru); B direct from global
__device__ __forceinline__ void mma_tile32x64_bfg(char* sm, int c, int kh,
                                                  int rg, int cg, int lane,
                                                  float acc[2][8][4]) {
    char* aHb = sm + GR_AH + (uint32_t)kh * 256 + (rg * 32 + (lane >> 2)) * G_PITCH + (lane & 3) * 4;
    char* aLb = sm + GR_AL + (uint32_t)kh * 256 + (rg * 32 + (lane >> 2)) * G_PITCH + (lane & 3) * 4;
    const uint2* bhB = g_Bgh + ((size_t)(c * 16 + kh * 8) * 16 + cg * 8) * 32 + lane;
    const uint2* blB = g_Bgl + ((size_t)(c * 16 + kh * 8) * 16 + cg * 8) * 32 + lane;
    #pragma unroll
    for (int s = 0; s < 8; ++s) {
        uint2 bh[8], bl[8];
        #pragma unroll
        for (int j = 0; j < 8; ++j) {
            bh[j] = __ldg(&bhB[(s * 16 + j) * 32]);
            bl[j] = __ldg(&blB[(s * 16 + j) * 32]);
        }
        #pragma unroll
        for (int rf = 0; rf < 2; ++rf) {
            const int ao = s * 32 + rf * 16 * G_PITCH;
            uint32_t ah0 = *(const uint32_t*)(aHb + ao);
            uint32_t ah1 = *(const uint32_t*)(aHb + ao + 8 * G_PITCH);
            uint32_t ah2 = *(const uint32_t*)(aHb + ao + 16);
            uint32_t ah3 = *(const uint32_t*)(aHb + ao + 8 * G_PITCH + 16);
            uint32_t al0 = *(const uint32_t*)(aLb + ao);
            uint32_t al1 = *(const uint32_t*)(aLb + ao + 8 * G_PITCH);
            uint32_t al2 = *(const uint32_t*)(aLb + ao + 16);
            uint32_t al3 = *(const uint32_t*)(aLb + ao + 8 * G_PITCH + 16);
            #pragma unroll
            for (int j = 0; j < 8; ++j) {
                MMA_BF16(acc[rf][j], ah0, ah1, ah2, ah3, bh[j].x, bh[j].y);
                MMA_BF16(acc[rf][j], ah0, ah1, ah2, ah3, bl[j].x, bl[j].y);
                MMA_BF16(acc[rf][j], al0, al1, al2, al3, bh[j].x, bh[j].y);
            }
        }
    }
}

// 16x64 warp tile, fp16 SINGLE-term (edge)
__device__ __forceinline__ void mma_tile16x64_fp1(char* sm, uint32_t aH,
                                                  int rg, int cg, int lane,
                                                  float acc[8][4]) {
    char* aHb = sm + aH + (rg * 16 + (lane >> 2)) * A_PITCH + (lane & 3) * 4;
    char* bb  = sm + EG_B + cg * 8 * 256 + lane * 8;
    #pragma unroll
    for (int s = 0; s < 8; ++s) {
        uint2 b[8];
        #pragma unroll
        for (int j = 0; j < 8; ++j)
            b[j] = *(const uint2*)(bb + s * 4096 + j * 256);
        const int ao = s * 32;
        uint32_t a0 = *(const uint32_t*)(aHb + ao);
        uint32_t a1 = *(const uint32_t*)(aHb + ao + 8 * A_PITCH);
        uint32_t a2 = *(const uint32_t*)(aHb + ao + 16);
        uint32_t a3 = *(const uint32_t*)(aHb + ao + 8 * A_PITCH + 16);
        #pragma unroll
        for (int j = 0; j < 8; ++j)
            MMA_F16(acc[j], a0, a1, a2, a3, b[j].x, b[j].y);
    }
}

// ---------------------------------------------------------------------------
__device__ __forceinline__ float gru_w(const float* Wi, const float* Wh,
                                       int c, int k, int n) {
    if (c == 0) return k < 128 ? Wi[(size_t)k * 384 + n] : Wh[(size_t)(k - 128) * 384 + n];
    if (c == 1) return k < 128 ? Wi[(size_t)k * 384 + 128 + n] : Wh[(size_t)(k - 128) * 384 + 128 + n];
    if (c == 2) return k < 128 ? Wi[(size_t)k * 384 + 256 + n] : 0.f;
    return k < 128 ? 0.f : Wh[(size_t)(k - 128) * 384 + 256 + n];
}

__global__ void prep_kernel(const float* __restrict__ W,
                            const float* __restrict__ Wi,
                            const float* __restrict__ Wh, int N_) {
    const int stride = gridDim.x * blockDim.x;
    const int tid0 = blockIdx.x * blockDim.x + threadIdx.x;
    const int TOT = 2 * 8 * 16 * 32;
    for (int i = tid0; i < TOT; i += stride) {
        int l = i & 31, j = (i >> 5) & 15, s = (i >> 9) & 7, c = i >> 12;
        int k = c * 128 + s * 16 + (l & 3) * 2;
        int n = j * 8 + (l >> 2);
        float w00 = W[(size_t)(k + 0) * D + n];
        float w01 = W[(size_t)(k + 1) * D + n];
        float w10 = W[(size_t)(k + 8) * D + n];
        float w11 = W[(size_t)(k + 9) * D + n];
        float h00 = __bfloat162float(__float2bfloat16_rn(w00));
        float h01 = __bfloat162float(__float2bfloat16_rn(w01));
        float h10 = __bfloat162float(__float2bfloat16_rn(w10));
        float h11 = __bfloat162float(__float2bfloat16_rn(w11));
        g_Bh[i] = make_uint2(pack_bf2(h00, h01), pack_bf2(h10, h11));
        g_Bl[i] = make_uint2(pack_bf2(w00 - h00, w01 - h01),
                             pack_bf2(w10 - h10, w11 - h11));
    }
    const int TOTF = 8 * 16 * 32;
    for (int i = tid0; i < TOTF; i += stride) {
        int l = i & 31, j = (i >> 5) & 15, s = (i >> 9) & 7;
        int k = 256 + s * 16 + (l & 3) * 2;
        int n = j * 8 + (l >> 2);
        g_Bf[i] = make_uint2(
            pack_h2(W[(size_t)(k + 0) * D + n], W[(size_t)(k + 1) * D + n]),
            pack_h2(W[(size_t)(k + 8) * D + n], W[(size_t)(k + 9) * D + n]));
    }
    const int TOTG = 4 * 16 * 16 * 32;
    for (int i = tid0; i < TOTG; i += stride) {
        int l = i & 31, j = (i >> 5) & 15, s = (i >> 9) & 15, c = i >> 13;
        int k = s * 16 + (l & 3) * 2;
        int n = j * 8 + (l >> 2);
        float w00 = gru_w(Wi, Wh, c, k + 0, n);
        float w01 = gru_w(Wi, Wh, c, k + 1, n);
        float w10 = gru_w(Wi, Wh, c, k + 8, n);
        float w11 = gru_w(Wi, Wh, c, k + 9, n);
        float h00 = __bfloat162float(__float2bfloat16_rn(w00));
        float h01 = __bfloat162float(__float2bfloat16_rn(w01));
        float h10 = __bfloat162float(__float2bfloat16_rn(w10));
        float h11 = __bfloat162float(__float2bfloat16_rn(w11));
        g_Bgh[i] = make_uint2(pack_bf2(h00, h01), pack_bf2(h10, h11));
        g_Bgl[i] = make_uint2(pack_bf2(w00 - h00, w01 - h01),
                              pack_bf2(w10 - h10, w11 - h11));
    }
    for (int i = tid0; i < N_; i += stride) g_count[i] = 0;
}

__global__ void hist_kernel(const int* __restrict__ rcv, int E_) {
    int i = blockIdx.x * blockDim.x + threadIdx.x;
    if (i < E_) atomicAdd(&g_count[rcv[i]], 1);
}

__global__ void scan_kernel(int N_, int E_) {
    __shared__ int wsum[32];
    __shared__ int s_carry;
    const int t = threadIdx.x;
    const int lane = t & 31, wid = t >> 5;
    if (t == 0) s_carry = 0;
    __syncthreads();
    const int rounds = (N_ + 1023) >> 10;
    for (int r = 0; r < rounds; ++r) {
        int i = r * 1024 + t;
        int v = (i < N_) ? g_count[i] : 0;
        int x = v;
        #pragma unroll
        for (int o = 1; o < 32; o <<= 1) {
            int y = __shfl_up_sync(0xFFFFFFFFu, x, o);
            if (lane >= o) x += y;
        }
        if (lane == 31) wsum[wid] = x;
        __syncthreads();
        if (wid == 0) {
            int w = wsum[lane];
            #pragma unroll
            for (int o = 1; o < 32; o <<= 1) {
                int y = __shfl_up_sync(0xFFFFFFFFu, w, o);
                if (lane >= o) w += y;
            }
            wsum[lane] = w;
        }
        __syncthreads();
        int excl = s_carry + (wid ? wsum[wid - 1] : 0) + x - v;
        if (i < N_) { g_off[i] = excl; g_cursor[i] = excl; }
        __syncthreads();
        if (t == 0) s_carry += wsum[31];
        __syncthreads();
    }
    if (t == 0) g_off[N_] = E_;
}

__global__ void scatter_kernel(const int* __restrict__ rcv, int E_) {
    int i = blockIdx.x * blockDim.x + threadIdx.x;
    if (i < E_) {
        int p = atomicAdd(&g_cursor[rcv[i]], 1);
        g_elist[p] = i;
    }
}

// ---------------------------------------------------------------------------
__global__ __launch_bounds__(512, 1) void node_proj_kernel(
    const float* __restrict__ nodes, int N_)
{
    extern __shared__ __align__(16) char sm[];
    const int t    = threadIdx.x;
    const int warp = t >> 5, lane = t & 31;
    const int n0   = blockIdx.x * 256;

    const int row = t >> 1, hf = t & 1;
    const int ng = min(n0 + row, N_ - 1);
    stage_A64_bf(sm + NP_AH + row * A_PITCH + hf * 128,
                 sm + NP_AL + row * A_PITCH + hf * 128,
                 nodes + (size_t)ng * D + hf * 64);
    __syncthreads();

    const int nr0 = n0 + warp * 16 + (lane >> 2);
    const int nr1 = nr0 + 8;
    const int cb  = (lane & 3) * 2;

    #pragma unroll
    for (int c = 0; c < 2; ++c) {
        float acc[16][4];
        #pragma unroll
        for (int j = 0; j < 16; ++j)
            #pragma unroll
            for (int q = 0; q < 4; ++q) acc[j][q] = 0.f;

        mma_rows16_g(sm, c, warp, lane, acc);

        float* P = c == 0 ? g_P1 : g_P2;
        #pragma unroll
        for (int j = 0; j < 16; ++j) {
            int col = j * 8 + cb;
            if (nr0 < N_) *(float2*)(P + (size_t)nr0 * D + col) = make_float2(acc[j][0], acc[j][1]);
            if (nr1 < N_) *(float2*)(P + (size_t)nr1 * D + col) = make_float2(acc[j][2], acc[j][3]);
        }
    }
}

// ---------------------------------------------------------------------------
// Edge (fp16 single-term): persistent, 128-edge tiles, dbl-buffered A(hi).
__global__ __launch_bounds__(512, 1) void edge_mma_kernel(
    const float* __restrict__ edges, const float* __restrict__ bvec,
    const int* __restrict__ snd, const int* __restrict__ rcv,
    float* __restrict__ msg, int E_, int ntiles)
{
    extern __shared__ __align__(16) char sm[];
    __shared__ float s_bias[128];

    const int t    = threadIdx.x;
    const int warp = t >> 5, lane = t & 31;
    const int rg   = warp >> 1, cg = warp & 1;

    if (t < 128) s_bias[t] = bvec[t];
    stage_B_eg(sm, t);

    const int srow = t >> 2, qt = t & 3;
    const uint32_t aRow = srow * A_PITCH + qt * 64;
    const uint32_t aOff[2] = {EG_A0, EG_A1};

    int tile = blockIdx.x;
    float4 v[8];
    {
        int eg = min(tile * 128 + srow, E_ - 1);
        ldg_A32(v, edges + (size_t)eg * D + qt * 32);
        cvt_sts_A32_fp1(sm + aOff[0] + aRow, v);
    }

    const int rfrag = rg * 16 + (lane >> 2);
    const int cb    = cg * 64 + (lane & 3) * 2;

    int buf = 0;
    for (; tile < ntiles; tile += gridDim.x) {
        int ntile = tile + gridDim.x;
        if (ntile < ntiles) {
            int eg = min(ntile * 128 + srow, E_ - 1);
            ldg_A32(v, edges + (size_t)eg * D + qt * 32);
        }
        const int er0 = tile * 128 + rfrag;
        const int er1 = er0 + 8;
        const int ec0 = min(er0, E_ - 1), ec1 = min(er1, E_ - 1);
        int sn0 = __ldg(&snd[ec0]), rc0 = __ldg(&rcv[ec0]);
        int sn1 = __ldg(&snd[ec1]), rc1 = __ldg(&rcv[ec1]);

        __syncthreads();

        float acc[8][4];
        #pragma unroll
        for (int j = 0; j < 8; ++j)
            #pragma unroll
            for (int q = 0; q < 4; ++q) acc[j][q] = 0.f;

        mma_tile16x64_fp1(sm, aOff[buf], rg, cg, lane, acc);

        #pragma unroll
        for (int hb = 0; hb < 2; ++hb) {
            int er = hb ? er1 : er0;
            if (er < E_) {
                const float* p1 = g_P1 + (size_t)(hb ? sn1 : sn0) * D;
                const float* p2 = g_P2 + (size_t)(hb ? rc1 : rc0) * D;
                float* mp = msg + (size_t)er * D;
                #pragma unroll
                for (int j = 0; j < 8; ++j) {
                    int col = cb + j * 8;
                    float2 q1 = *(const float2*)(p1 + col);
                    float2 q2 = *(const float2*)(p2 + col);
                    float2 o;
                    o.x = fmaxf(acc[j][hb * 2 + 0] + q1.x + q2.x + s_bias[col], 0.f);
                    o.y = fmaxf(acc[j][hb * 2 + 1] + q1.y + q2.y + s_bias[col + 1], 0.f);
                    *(float2*)(mp + col) = o;
                }
            }
        }

        if (ntile < ntiles) cvt_sts_A32_fp1(sm + aOff[buf ^ 1] + aRow, v);
        buf ^= 1;
    }
}

// ---------------------------------------------------------------------------
__global__ __launch_bounds__(128) void aggregate_kernel(const float* __restrict__ msg, int N_) {
    const int n = blockIdx.x;
    const int t = threadIdx.x;
    const int s = g_off[n], e = g_off[n + 1];
    float a0 = 0.f, a1 = 0.f, a2 = 0.f, a3 = 0.f;
    int i = s;
    for (; i + 4 <= e; i += 4) {
        int i0 = __ldg(&g_elist[i]);
        int i1 = __ldg(&g_elist[i + 1]);
        int i2 = __ldg(&g_elist[i + 2]);
        int i3 = __ldg(&g_elist[i + 3]);
        a0 += __ldg(&msg[(size_t)i0 * D + t]);
        a1 += __ldg(&msg[(size_t)i1 * D + t]);
        a2 += __ldg(&msg[(size_t)i2 * D + t]);
        a3 += __ldg(&msg[(size_t)i3 * D + t]);
    }
    for (; i < e; ++i) a0 += __ldg(&msg[(size_t)__ldg(&g_elist[i]) * D + t]);
    g_recv[(size_t)n * D + t] = (a0 + a1) + (a2 + a3);
}

// ---------------------------------------------------------------------------
// GRU gate GEMMs (bf16 3-term; B direct from global) with FUSED elementwise
// finisher at chunk 3: each thread re-reads the P1/P2/P3 values it wrote.
__global__ __launch_bounds__(256, 1) void gru_mma_kernel(
    const float* __restrict__ nodes, const float* __restrict__ bi,
    const float* __restrict__ bhn, float* __restrict__ out, int N_)
{
    extern __shared__ __align__(16) char sm[];
    const int t    = threadIdx.x;
    const int warp = t >> 5, lane = t & 31;
    const int n0   = blockIdx.x * 128;
    const int rg   = warp >> 1, cg = warp & 1;

    {
        const int row = t >> 1, hf = t & 1;
        const int ng = min(n0 + row, N_ - 1);
        #pragma unroll
        for (int qq = 0; qq < 2; ++qq) {
            int q = hf * 2 + qq;
            const float* src = (q < 2) ? (g_recv + (size_t)ng * D + q * 64)
                                       : (nodes + (size_t)ng * D + (q - 2) * 64);
            stage_A64_bf(sm + GR_AH + row * G_PITCH + q * 128,
                         sm + GR_AL + row * G_PITCH + q * 128, src);
        }
    }
    __syncthreads();

    const int cb = cg * 64 + (lane & 3) * 2;

    #pragma unroll
    for (int c = 0; c < 4; ++c) {
        const int kh_lo = (c == 3) ? 1 : 0;
        const int kh_hi = (c == 2) ? 0 : 1;

        float acc[2][8][4];
        #pragma unroll
        for (int rf = 0; rf < 2; ++rf)
            #pragma unroll
            for (int j = 0; j < 8; ++j)
                #pragma unroll
                for (int q = 0; q < 4; ++q) acc[rf][j][q] = 0.f;

        for (int kh = kh_lo; kh <= kh_hi; ++kh)
            mma_tile32x64_bfg(sm, c, kh, rg, cg, lane, acc);

        if (c < 3) {
            float* P = (c == 0) ? g_P1 : (c == 1) ? g_P2 : g_P3;
            #pragma unroll
            for (int rf = 0; rf < 2; ++rf)
                #pragma unroll
                for (int hb = 0; hb < 2; ++hb) {
                    int nr = n0 + rg * 32 + rf * 16 + (lane >> 2) + hb * 8;
                    if (nr < N_) {
                        #pragma unroll
                        for (int j = 0; j < 8; ++j) {
                            int col = cb + j * 8;
                            *(float2*)(P + (size_t)nr * D + col) =
                                make_float2(acc[rf][j][hb * 2], acc[rf][j][hb * 2 + 1]);
                        }
                    }
                }
        } else {
            // fused GRU finisher: acc = h_n pre-bias; read own P1/P2/P3
            #pragma unroll
            for (int rf = 0; rf < 2; ++rf)
                #pragma unroll
                for (int hb = 0; hb < 2; ++hb) {
                    int nr = n0 + rg * 32 + rf * 16 + (lane >> 2) + hb * 8;
                    if (nr < N_) {
                        #pragma unroll
                        for (int j = 0; j < 8; ++j) {
                            int col = cb + j * 8;
                            size_t idx = (size_t)nr * D + col;
                            float2 p1 = *(const float2*)(g_P1 + idx);
                            float2 p2 = *(const float2*)(g_P2 + idx);
                            float2 p3 = *(const float2*)(g_P3 + idx);
                            float2 nd = *(const float2*)(nodes + idx);
                            float2 o;
                            {
                                float r = 1.f / (1.f + expf(-(p1.x + __ldg(&bi[col]))));
                                float z = 1.f / (1.f + expf(-(p2.x + __ldg(&bi[128 + col]))));
                                float nn = tanhf(p3.x + __ldg(&bi[256 + col]) +
                                                 r * (acc[rf][j][hb * 2] + __ldg(&bhn[col])));
                                o.x = (1.f - z) * nn + z * nd.x;
                            }
                            {
                                float r = 1.f / (1.f + expf(-(p1.y + __ldg(&bi[col + 1]))));
                                float z = 1.f / (1.f + expf(-(p2.y + __ldg(&bi[129 + col]))));
                                float nn = tanhf(p3.y + __ldg(&bi[257 + col]) +
                                                 r * (acc[rf][j][hb * 2 + 1] + __ldg(&bhn[col + 1])));
                                o.y = (1.f - z) * nn + z * nd.y;
                            }
                            *(float2*)(out + idx) = o;
                        }
                    }
                }
        }
    }
}

// ---------------------------------------------------------------------------
extern "C" void kernel_launch(void* const* d_in, const int* in_sizes, int n_in,
                              void* d_out, int out_size)
{
    const float* nodes  = (const float*)d_in[0];
    const float* edges  = (const float*)d_in[1];
    const float* W_edge = (const float*)d_in[2];
    const float* b_edge = (const float*)d_in[3];
    const float* Wi     = (const float*)d_in[4];
    const float* bi     = (const float*)d_in[5];
    const float* Wh     = (const float*)d_in[6];
    const float* bh_n   = (const float*)d_in[7];
    const int*   snd    = (const int*)d_in[8];
    const int*   rcv    = (const int*)d_in[9];

    const int N_ = in_sizes[0] / D;
    const int E_ = in_sizes[8];

    float* new_nodes = (float*)d_out;
    float* messages  = (float*)d_out + (size_t)N_ * D;

    cudaFuncSetAttribute(node_proj_kernel,
                         cudaFuncAttributeMaxDynamicSharedMemorySize, NP_TOTAL);
    cudaFuncSetAttribute(edge_mma_kernel,
                         cudaFuncAttributeMaxDynamicSharedMemorySize, EG_TOTAL);
    cudaFuncSetAttribute(gru_mma_kernel,
                         cudaFuncAttributeMaxDynamicSharedMemorySize, GR_TOTAL);

    const int ntiles = (E_ + 127) / 128;
    const int egrid  = ntiles < 148 ? ntiles : 148;

    prep_kernel<<<96, 256>>>(W_edge, Wi, Wh, N_);
    node_proj_kernel<<<(N_ + 255) / 256, 512, NP_TOTAL>>>(nodes, N_);
    hist_kernel<<<(E_ + 255) / 256, 256>>>(rcv, E_);
    edge_mma_kernel<<<egrid, 512, EG_TOTAL>>>(
        edges, b_edge, snd, rcv, messages, E_, ntiles);
    scan_kernel<<<1, 1024>>>(N_, E_);
    scatter_kernel<<<(E_ + 255) / 256, 256>>>(rcv, E_);
    aggregate_kernel<<<N_, 128>>>(messages, N_);
    gru_mma_kernel<<<(N_ + 127) / 128, 256, GR_TOTAL>>>(nodes, bi, bh_n,
                                                        new_nodes, N_);
}

// round 17
// speedup vs baseline: 1.0842x; 1.0653x over previous
#include <cuda_runtime.h>
#include <cuda_fp16.h>
#include <cuda_bf16.h>
#include <cstdint>
#include <math.h>

#define D      128
#define N_MAX  20000
#define E_MAX  640000

// ---------------- device scratch ----------------
__device__ float g_recv[(size_t)N_MAX * D];
__device__ float g_P1[(size_t)N_MAX * D];
__device__ float g_P2[(size_t)N_MAX * D];
__device__ float g_P3[(size_t)N_MAX * D];
__device__ float g_P4[(size_t)N_MAX * D];
__device__ uint2 g_Bh[2 * 8 * 16 * 32];
__device__ uint2 g_Bl[2 * 8 * 16 * 32];
__device__ uint2 g_Bf[8 * 16 * 32];
__device__ uint2 g_Bgh[4 * 16 * 16 * 32];
__device__ uint2 g_Bgl[4 * 16 * 16 * 32];
__device__ int   g_count[N_MAX];
__device__ int   g_off[N_MAX + 1];
__device__ int   g_cursor[N_MAX];
__device__ int   g_elist[E_MAX];

__device__ __forceinline__ uint32_t pack_bf2(float a, float b) {
    __nv_bfloat162 h = __floats2bfloat162_rn(a, b);
    return *(uint32_t*)&h;
}
__device__ __forceinline__ uint32_t pack_h2(float a, float b) {
    __half2 h = __floats2half2_rn(a, b);
    return *(uint32_t*)&h;
}

#define MMA_BF16(d, a0, a1, a2, a3, b0, b1)                                    \
    asm volatile("mma.sync.aligned.m16n8k16.row.col.f32.bf16.bf16.f32 "        \
                 "{%0,%1,%2,%3}, {%4,%5,%6,%7}, {%8,%9}, {%0,%1,%2,%3};"       \
                 : "+f"((d)[0]), "+f"((d)[1]), "+f"((d)[2]), "+f"((d)[3])      \
                 : "r"(a0), "r"(a1), "r"(a2), "r"(a3), "r"(b0), "r"(b1))
#define MMA_F16(d, a0, a1, a2, a3, b0, b1)                                     \
    asm volatile("mma.sync.aligned.m16n8k16.row.col.f32.f16.f16.f32 "          \
                 "{%0,%1,%2,%3}, {%4,%5,%6,%7}, {%8,%9}, {%0,%1,%2,%3};"       \
                 : "+f"((d)[0]), "+f"((d)[1]), "+f"((d)[2]), "+f"((d)[3])      \
                 : "r"(a0), "r"(a1), "r"(a2), "r"(a3), "r"(b0), "r"(b1))

// ---------------- smem layouts ----------------
#define A_PITCH 272

// node_proj (bf16 3-term): A only in smem; B direct from global
#define NP_AH   0
#define NP_AL   (256 * A_PITCH)
#define NP_TOTAL (2 * 256 * A_PITCH)

// edge (fp16 single-term): persistent, 128-edge tiles (CSR order),
// B staged once, A double-buffered.
#define EG_B    0
#define EG_ASZ  (128 * A_PITCH)
#define EG_A0   32768
#define EG_A1   (32768 + EG_ASZ)
#define EG_TOTAL (32768 + 2 * EG_ASZ)            // 102,400 B

// gru (bf16 3-term): A only in smem; B direct from global
#define G_PITCH 528
#define GR_AH   0
#define GR_AL   (128 * G_PITCH)
#define GR_TOTAL (2 * 128 * G_PITCH)

// ---- staging ----
__device__ __forceinline__ void stage_A64_bf(char* awh, char* awl, const float* src) {
    #pragma unroll
    for (int q = 0; q < 8; ++q) {
        float4 v0 = __ldg((const float4*)(src + q * 8));
        float4 v1 = __ldg((const float4*)(src + q * 8 + 4));
        float h0 = __bfloat162float(__float2bfloat16_rn(v0.x));
        float h1 = __bfloat162float(__float2bfloat16_rn(v0.y));
        float h2 = __bfloat162float(__float2bfloat16_rn(v0.z));
        float h3 = __bfloat162float(__float2bfloat16_rn(v0.w));
        float h4 = __bfloat162float(__float2bfloat16_rn(v1.x));
        float h5 = __bfloat162float(__float2bfloat16_rn(v1.y));
        float h6 = __bfloat162float(__float2bfloat16_rn(v1.z));
        float h7 = __bfloat162float(__float2bfloat16_rn(v1.w));
        *(uint4*)(awh + q * 16) = make_uint4(pack_bf2(h0, h1), pack_bf2(h2, h3),
                                             pack_bf2(h4, h5), pack_bf2(h6, h7));
        *(uint4*)(awl + q * 16) = make_uint4(pack_bf2(v0.x - h0, v0.y - h1),
                                             pack_bf2(v0.z - h2, v0.w - h3),
                                             pack_bf2(v1.x - h4, v1.y - h5),
                                             pack_bf2(v1.z - h6, v1.w - h7));
    }
}

__device__ __forceinline__ void ldg_A32(float4* v, const float* src) {
    #pragma unroll
    for (int q = 0; q < 8; ++q) v[q] = __ldg((const float4*)(src + q * 4));
}
__device__ __forceinline__ void cvt_sts_A32_fp1(char* awh, const float4* v) {
    #pragma unroll
    for (int q = 0; q < 4; ++q) {
        float4 v0 = v[q * 2], v1 = v[q * 2 + 1];
        *(uint4*)(awh + q * 16) = make_uint4(pack_h2(v0.x, v0.y), pack_h2(v0.z, v0.w),
                                             pack_h2(v1.x, v1.y), pack_h2(v1.z, v1.w));
    }
}

__device__ __forceinline__ void stage_B_eg(char* sm, int t) {
    const uint4* gb = (const uint4*)g_Bf;
    #pragma unroll
    for (int q = 0; q < 4; ++q) {
        int i = t + q * 512;
        *(uint4*)(sm + EG_B + i * 16) = __ldg(&gb[i]);
    }
}

// 16x128 warp tile, bf16 3-term; B direct from global
__device__ __forceinline__ void mma_rows16_g(char* sm, int c, int warp, int lane,
                                             float acc[16][4]) {
    char* aHip = sm + NP_AH + (warp * 16 + (lane >> 2)) * A_PITCH + (lane & 3) * 4;
    char* aLip = sm + NP_AL + (warp * 16 + (lane >> 2)) * A_PITCH + (lane & 3) * 4;
    const uint2* bhB = g_Bh + ((size_t)c * 8 * 16) * 32 + lane;
    const uint2* blB = g_Bl + ((size_t)c * 8 * 16) * 32 + lane;
    #pragma unroll
    for (int s = 0; s < 8; ++s) {
        uint32_t ah0 = *(const uint32_t*)(aHip + s * 32);
        uint32_t ah1 = *(const uint32_t*)(aHip + s * 32 + 8 * A_PITCH);
        uint32_t ah2 = *(const uint32_t*)(aHip + s * 32 + 16);
        uint32_t ah3 = *(const uint32_t*)(aHip + s * 32 + 8 * A_PITCH + 16);
        uint32_t al0 = *(const uint32_t*)(aLip + s * 32);
        uint32_t al1 = *(const uint32_t*)(aLip + s * 32 + 8 * A_PITCH);
        uint32_t al2 = *(const uint32_t*)(aLip + s * 32 + 16);
        uint32_t al3 = *(const uint32_t*)(aLip + s * 32 + 8 * A_PITCH + 16);
        #pragma unroll
        for (int j = 0; j < 16; ++j) {
            uint2 bh = __ldg(&bhB[(s * 16 + j) * 32]);
            uint2 bl = __ldg(&blB[(s * 16 + j) * 32]);
            MMA_BF16(acc[j], ah0, ah1, ah2, ah3, bh.x, bh.y);
            MMA_BF16(acc[j], ah0, ah1, ah2, ah3, bl.x, bl.y);
            MMA_BF16(acc[j], al0, al1, al2, al3, bh.x, bh.y);
        }
    }
}

// 32x64 warp tile, bf16 3-term (gru); B direct from global
__device__ __forceinline__ void mma_tile32x64_bfg(char* sm, int c, int kh,
                                                  int rg, int cg, int lane,
                                                  float acc[2][8][4]) {
    char* aHb = sm + GR_AH + (uint32_t)kh * 256 + (rg * 32 + (lane >> 2)) * G_PITCH + (lane & 3) * 4;
    char* aLb = sm + GR_AL + (uint32_t)kh * 256 + (rg * 32 + (lane >> 2)) * G_PITCH + (lane & 3) * 4;
    const uint2* bhB = g_Bgh + ((size_t)(c * 16 + kh * 8) * 16 + cg * 8) * 32 + lane;
    const uint2* blB = g_Bgl + ((size_t)(c * 16 + kh * 8) * 16 + cg * 8) * 32 + lane;
    #pragma unroll
    for (int s = 0; s < 8; ++s) {
        uint2 bh[8], bl[8];
        #pragma unroll
        for (int j = 0; j < 8; ++j) {
            bh[j] = __ldg(&bhB[(s * 16 + j) * 32]);
            bl[j] = __ldg(&blB[(s * 16 + j) * 32]);
        }
        #pragma unroll
        for (int rf = 0; rf < 2; ++rf) {
            const int ao = s * 32 + rf * 16 * G_PITCH;
            uint32_t ah0 = *(const uint32_t*)(aHb + ao);
            uint32_t ah1 = *(const uint32_t*)(aHb + ao + 8 * G_PITCH);
            uint32_t ah2 = *(const uint32_t*)(aHb + ao + 16);
            uint32_t ah3 = *(const uint32_t*)(aHb + ao + 8 * G_PITCH + 16);
            uint32_t al0 = *(const uint32_t*)(aLb + ao);
            uint32_t al1 = *(const uint32_t*)(aLb + ao + 8 * G_PITCH);
            uint32_t al2 = *(const uint32_t*)(aLb + ao + 16);
            uint32_t al3 = *(const uint32_t*)(aLb + ao + 8 * G_PITCH + 16);
            #pragma unroll
            for (int j = 0; j < 8; ++j) {
                MMA_BF16(acc[rf][j], ah0, ah1, ah2, ah3, bh[j].x, bh[j].y);
                MMA_BF16(acc[rf][j], ah0, ah1, ah2, ah3, bl[j].x, bl[j].y);
                MMA_BF16(acc[rf][j], al0, al1, al2, al3, bh[j].x, bh[j].y);
            }
        }
    }
}

// 16x64 warp tile, fp16 single-term (edge)
__device__ __forceinline__ void mma_tile16x64_fp1(char* sm, uint32_t aH,
                                                  int rg, int cg, int lane,
                                                  float acc[8][4]) {
    char* aHb = sm + aH + (rg * 16 + (lane >> 2)) * A_PITCH + (lane & 3) * 4;
    char* bb  = sm + EG_B + cg * 8 * 256 + lane * 8;
    #pragma unroll
    for (int s = 0; s < 8; ++s) {
        uint2 b[8];
        #pragma unroll
        for (int j = 0; j < 8; ++j)
            b[j] = *(const uint2*)(bb + s * 4096 + j * 256);
        const int ao = s * 32;
        uint32_t a0 = *(const uint32_t*)(aHb + ao);
        uint32_t a1 = *(const uint32_t*)(aHb + ao + 8 * A_PITCH);
        uint32_t a2 = *(const uint32_t*)(aHb + ao + 16);
        uint32_t a3 = *(const uint32_t*)(aHb + ao + 8 * A_PITCH + 16);
        #pragma unroll
        for (int j = 0; j < 8; ++j)
            MMA_F16(acc[j], a0, a1, a2, a3, b[j].x, b[j].y);
    }
}

// ---------------------------------------------------------------------------
__device__ __forceinline__ float gru_w(const float* Wi, const float* Wh,
                                       int c, int k, int n) {
    if (c == 0) return k < 128 ? Wi[(size_t)k * 384 + n] : Wh[(size_t)(k - 128) * 384 + n];
    if (c == 1) return k < 128 ? Wi[(size_t)k * 384 + 128 + n] : Wh[(size_t)(k - 128) * 384 + 128 + n];
    if (c == 2) return k < 128 ? Wi[(size_t)k * 384 + 256 + n] : 0.f;
    return k < 128 ? 0.f : Wh[(size_t)(k - 128) * 384 + 256 + n];
}

__global__ void prep_kernel(const float* __restrict__ W,
                            const float* __restrict__ Wi,
                            const float* __restrict__ Wh, int N_) {
    const int stride = gridDim.x * blockDim.x;
    const int tid0 = blockIdx.x * blockDim.x + threadIdx.x;
    const int TOT = 2 * 8 * 16 * 32;
    for (int i = tid0; i < TOT; i += stride) {
        int l = i & 31, j = (i >> 5) & 15, s = (i >> 9) & 7, c = i >> 12;
        int k = c * 128 + s * 16 + (l & 3) * 2;
        int n = j * 8 + (l >> 2);
        float w00 = W[(size_t)(k + 0) * D + n];
        float w01 = W[(size_t)(k + 1) * D + n];
        float w10 = W[(size_t)(k + 8) * D + n];
        float w11 = W[(size_t)(k + 9) * D + n];
        float h00 = __bfloat162float(__float2bfloat16_rn(w00));
        float h01 = __bfloat162float(__float2bfloat16_rn(w01));
        float h10 = __bfloat162float(__float2bfloat16_rn(w10));
        float h11 = __bfloat162float(__float2bfloat16_rn(w11));
        g_Bh[i] = make_uint2(pack_bf2(h00, h01), pack_bf2(h10, h11));
        g_Bl[i] = make_uint2(pack_bf2(w00 - h00, w01 - h01),
                             pack_bf2(w10 - h10, w11 - h11));
    }
    const int TOTF = 8 * 16 * 32;
    for (int i = tid0; i < TOTF; i += stride) {
        int l = i & 31, j = (i >> 5) & 15, s = (i >> 9) & 7;
        int k = 256 + s * 16 + (l & 3) * 2;
        int n = j * 8 + (l >> 2);
        g_Bf[i] = make_uint2(
            pack_h2(W[(size_t)(k + 0) * D + n], W[(size_t)(k + 1) * D + n]),
            pack_h2(W[(size_t)(k + 8) * D + n], W[(size_t)(k + 9) * D + n]));
    }
    const int TOTG = 4 * 16 * 16 * 32;
    for (int i = tid0; i < TOTG; i += stride) {
        int l = i & 31, j = (i >> 5) & 15, s = (i >> 9) & 15, c = i >> 13;
        int k = s * 16 + (l & 3) * 2;
        int n = j * 8 + (l >> 2);
        float w00 = gru_w(Wi, Wh, c, k + 0, n);
        float w01 = gru_w(Wi, Wh, c, k + 1, n);
        float w10 = gru_w(Wi, Wh, c, k + 8, n);
        float w11 = gru_w(Wi, Wh, c, k + 9, n);
        float h00 = __bfloat162float(__float2bfloat16_rn(w00));
        float h01 = __bfloat162float(__float2bfloat16_rn(w01));
        float h10 = __bfloat162float(__float2bfloat16_rn(w10));
        float h11 = __bfloat162float(__float2bfloat16_rn(w11));
        g_Bgh[i] = make_uint2(pack_bf2(h00, h01), pack_bf2(h10, h11));
        g_Bgl[i] = make_uint2(pack_bf2(w00 - h00, w01 - h01),
                              pack_bf2(w10 - h10, w11 - h11));
    }
    for (int i = tid0; i < N_; i += stride) g_count[i] = 0;
}

__global__ void hist_kernel(const int* __restrict__ rcv, int E_) {
    int i = blockIdx.x * blockDim.x + threadIdx.x;
    if (i < E_) atomicAdd(&g_count[rcv[i]], 1);
}

__global__ void scan_kernel(int N_, int E_) {
    __shared__ int wsum[32];
    __shared__ int s_carry;
    const int t = threadIdx.x;
    const int lane = t & 31, wid = t >> 5;
    if (t == 0) s_carry = 0;
    __syncthreads();
    const int rounds = (N_ + 1023) >> 10;
    for (int r = 0; r < rounds; ++r) {
        int i = r * 1024 + t;
        int v = (i < N_) ? g_count[i] : 0;
        int x = v;
        #pragma unroll
        for (int o = 1; o < 32; o <<= 1) {
            int y = __shfl_up_sync(0xFFFFFFFFu, x, o);
            if (lane >= o) x += y;
        }
        if (lane == 31) wsum[wid] = x;
        __syncthreads();
        if (wid == 0) {
            int w = wsum[lane];
            #pragma unroll
            for (int o = 1; o < 32; o <<= 1) {
                int y = __shfl_up_sync(0xFFFFFFFFu, w, o);
                if (lane >= o) w += y;
            }
            wsum[lane] = w;
        }
        __syncthreads();
        int excl = s_carry + (wid ? wsum[wid - 1] : 0) + x - v;
        if (i < N_) { g_off[i] = excl; g_cursor[i] = excl; }
        __syncthreads();
        if (t == 0) s_carry += wsum[31];
        __syncthreads();
    }
    if (t == 0) g_off[N_] = E_;
}

__global__ void scatter_kernel(const int* __restrict__ rcv, int E_) {
    int i = blockIdx.x * blockDim.x + threadIdx.x;
    if (i < E_) {
        int p = atomicAdd(&g_cursor[rcv[i]], 1);
        g_elist[p] = i;
    }
}

// ---------------------------------------------------------------------------
__global__ __launch_bounds__(512, 1) void node_proj_kernel(
    const float* __restrict__ nodes, int N_)
{
    extern __shared__ __align__(16) char sm[];
    const int t    = threadIdx.x;
    const int warp = t >> 5, lane = t & 31;
    const int n0   = blockIdx.x * 256;

    const int row = t >> 1, hf = t & 1;
    const int ng = min(n0 + row, N_ - 1);
    stage_A64_bf(sm + NP_AH + row * A_PITCH + hf * 128,
                 sm + NP_AL + row * A_PITCH + hf * 128,
                 nodes + (size_t)ng * D + hf * 64);
    __syncthreads();

    const int nr0 = n0 + warp * 16 + (lane >> 2);
    const int nr1 = nr0 + 8;
    const int cb  = (lane & 3) * 2;

    #pragma unroll
    for (int c = 0; c < 2; ++c) {
        float acc[16][4];
        #pragma unroll
        for (int j = 0; j < 16; ++j)
            #pragma unroll
            for (int q = 0; q < 4; ++q) acc[j][q] = 0.f;

        mma_rows16_g(sm, c, warp, lane, acc);

        float* P = c == 0 ? g_P1 : g_P2;
        #pragma unroll
        for (int j = 0; j < 16; ++j) {
            int col = j * 8 + cb;
            if (nr0 < N_) *(float2*)(P + (size_t)nr0 * D + col) = make_float2(acc[j][0], acc[j][1]);
            if (nr1 < N_) *(float2*)(P + (size_t)nr1 * D + col) = make_float2(acc[j][2], acc[j][3]);
        }
    }
}

// ---------------------------------------------------------------------------
// Edge (fp16 single-term): persistent, 128-edge tiles in CSR (g_elist) order
// so P2[rcv] gathers hit few distinct rows per tile. Double-buffered A.
__global__ __launch_bounds__(512, 1) void edge_mma_kernel(
    const float* __restrict__ edges, const float* __restrict__ bvec,
    const int* __restrict__ snd, const int* __restrict__ rcv,
    float* __restrict__ msg, int E_, int ntiles)
{
    extern __shared__ __align__(16) char sm[];
    __shared__ float s_bias[128];

    const int t    = threadIdx.x;
    const int warp = t >> 5, lane = t & 31;
    const int rg   = warp >> 1, cg = warp & 1;

    if (t < 128) s_bias[t] = bvec[t];
    stage_B_eg(sm, t);

    const int srow = t >> 2, qt = t & 3;
    const uint32_t aRow = srow * A_PITCH + qt * 64;
    const uint32_t aOff[2] = {EG_A0, EG_A1};

    int tile = blockIdx.x;
    float4 v[8];
    {
        int e = __ldg(&g_elist[min(tile * 128 + srow, E_ - 1)]);
        ldg_A32(v, edges + (size_t)e * D + qt * 32);
        cvt_sts_A32_fp1(sm + aOff[0] + aRow, v);
    }

    const int rfrag = rg * 16 + (lane >> 2);
    const int cb    = cg * 64 + (lane & 3) * 2;

    int buf = 0;
    for (; tile < ntiles; tile += gridDim.x) {
        int ntile = tile + gridDim.x;
        if (ntile < ntiles) {
            int e = __ldg(&g_elist[min(ntile * 128 + srow, E_ - 1)]);
            ldg_A32(v, edges + (size_t)e * D + qt * 32);
        }
        // this tile's epilogue edge ids + gather indices (prefetched)
        const int p0 = tile * 128 + rfrag;
        const int p1p = p0 + 8;
        const int e0 = __ldg(&g_elist[min(p0, E_ - 1)]);
        const int e1 = __ldg(&g_elist[min(p1p, E_ - 1)]);
        int sn0 = __ldg(&snd[e0]), rc0 = __ldg(&rcv[e0]);
        int sn1 = __ldg(&snd[e1]), rc1 = __ldg(&rcv[e1]);

        __syncthreads();

        float acc[8][4];
        #pragma unroll
        for (int j = 0; j < 8; ++j)
            #pragma unroll
            for (int q = 0; q < 4; ++q) acc[j][q] = 0.f;

        mma_tile16x64_fp1(sm, aOff[buf], rg, cg, lane, acc);

        #pragma unroll
        for (int hb = 0; hb < 2; ++hb) {
            int p = hb ? p1p : p0;
            if (p < E_) {
                int e = hb ? e1 : e0;
                const float* q1 = g_P1 + (size_t)(hb ? sn1 : sn0) * D;
                const float* q2 = g_P2 + (size_t)(hb ? rc1 : rc0) * D;
                float* mp = msg + (size_t)e * D;
                #pragma unroll
                for (int j = 0; j < 8; ++j) {
                    int col = cb + j * 8;
                    float2 a1 = *(const float2*)(q1 + col);
                    float2 a2 = *(const float2*)(q2 + col);
                    float2 o;
                    o.x = fmaxf(acc[j][hb * 2 + 0] + a1.x + a2.x + s_bias[col], 0.f);
                    o.y = fmaxf(acc[j][hb * 2 + 1] + a1.y + a2.y + s_bias[col + 1], 0.f);
                    *(float2*)(mp + col) = o;
                }
            }
        }

        if (ntile < ntiles) cvt_sts_A32_fp1(sm + aOff[buf ^ 1] + aRow, v);
        buf ^= 1;
    }
}

// ---------------------------------------------------------------------------
__global__ __launch_bounds__(128) void aggregate_kernel(const float* __restrict__ msg, int N_) {
    const int n = blockIdx.x;
    const int t = threadIdx.x;
    const int s = g_off[n], e = g_off[n + 1];
    float a0 = 0.f, a1 = 0.f, a2 = 0.f, a3 = 0.f;
    int i = s;
    for (; i + 4 <= e; i += 4) {
        int i0 = __ldg(&g_elist[i]);
        int i1 = __ldg(&g_elist[i + 1]);
        int i2 = __ldg(&g_elist[i + 2]);
        int i3 = __ldg(&g_elist[i + 3]);
        a0 += __ldg(&msg[(size_t)i0 * D + t]);
        a1 += __ldg(&msg[(size_t)i1 * D + t]);
        a2 += __ldg(&msg[(size_t)i2 * D + t]);
        a3 += __ldg(&msg[(size_t)i3 * D + t]);
    }
    for (; i < e; ++i) a0 += __ldg(&msg[(size_t)__ldg(&g_elist[i]) * D + t]);
    g_recv[(size_t)n * D + t] = (a0 + a1) + (a2 + a3);
}

// ---------------------------------------------------------------------------
// GRU gate GEMMs (bf16 3-term; B direct from global) — R14 verified, unfused
__global__ __launch_bounds__(256, 1) void gru_mma_kernel(
    const float* __restrict__ nodes, int N_)
{
    extern __shared__ __align__(16) char sm[];
    const int t    = threadIdx.x;
    const int warp = t >> 5, lane = t & 31;
    const int n0   = blockIdx.x * 128;
    const int rg   = warp >> 1, cg = warp & 1;

    {
        const int row = t >> 1, hf = t & 1;
        const int ng = min(n0 + row, N_ - 1);
        #pragma unroll
        for (int qq = 0; qq < 2; ++qq) {
            int q = hf * 2 + qq;
            const float* src = (q < 2) ? (g_recv + (size_t)ng * D + q * 64)
                                       : (nodes + (size_t)ng * D + (q - 2) * 64);
            stage_A64_bf(sm + GR_AH + row * G_PITCH + q * 128,
                         sm + GR_AL + row * G_PITCH + q * 128, src);
        }
    }
    __syncthreads();

    const int cb = cg * 64 + (lane & 3) * 2;

    #pragma unroll
    for (int c = 0; c < 4; ++c) {
        const int kh_lo = (c == 3) ? 1 : 0;
        const int kh_hi = (c == 2) ? 0 : 1;

        float acc[2][8][4];
        #pragma unroll
        for (int rf = 0; rf < 2; ++rf)
            #pragma unroll
            for (int j = 0; j < 8; ++j)
                #pragma unroll
                for (int q = 0; q < 4; ++q) acc[rf][j][q] = 0.f;

        for (int kh = kh_lo; kh <= kh_hi; ++kh)
            mma_tile32x64_bfg(sm, c, kh, rg, cg, lane, acc);

        float* P = (c == 0) ? g_P1 : (c == 1) ? g_P2 : (c == 2) ? g_P3 : g_P4;
        #pragma unroll
        for (int rf = 0; rf < 2; ++rf)
            #pragma unroll
            for (int hb = 0; hb < 2; ++hb) {
                int nr = n0 + rg * 32 + rf * 16 + (lane >> 2) + hb * 8;
                if (nr < N_) {
                    #pragma unroll
                    for (int j = 0; j < 8; ++j) {
                        int col = cb + j * 8;
                        *(float2*)(P + (size_t)nr * D + col) =
                            make_float2(acc[rf][j][hb * 2], acc[rf][j][hb * 2 + 1]);
                    }
                }
            }
    }
}

__global__ __launch_bounds__(256) void gru_elem_kernel(
    const float* __restrict__ nodes, const float* __restrict__ bi,
    const float* __restrict__ bhn, float* __restrict__ out, int total)
{
    int i = blockIdx.x * blockDim.x + threadIdx.x;
    if (i >= total) return;
    int col = i & 127;
    float pre_r = g_P1[i] + __ldg(&bi[col]);
    float pre_z = g_P2[i] + __ldg(&bi[128 + col]);
    float i_n   = g_P3[i] + __ldg(&bi[256 + col]);
    float h_n   = g_P4[i] + __ldg(&bhn[col]);
    float r = 1.f / (1.f + expf(-pre_r));
    float z = 1.f / (1.f + expf(-pre_z));
    float n = tanhf(i_n + r * h_n);
    float h = __ldg(&nodes[i]);
    out[i] = (1.f - z) * n + z * h;
}

// ---------------------------------------------------------------------------
extern "C" void kernel_launch(void* const* d_in, const int* in_sizes, int n_in,
                              void* d_out, int out_size)
{
    const float* nodes  = (const float*)d_in[0];
    const float* edges  = (const float*)d_in[1];
    const float* W_edge = (const float*)d_in[2];
    const float* b_edge = (const float*)d_in[3];
    const float* Wi     = (const float*)d_in[4];
    const float* bi     = (const float*)d_in[5];
    const float* Wh     = (const float*)d_in[6];
    const float* bh_n   = (const float*)d_in[7];
    const int*   snd    = (const int*)d_in[8];
    const int*   rcv    = (const int*)d_in[9];

    const int N_ = in_sizes[0] / D;
    const int E_ = in_sizes[8];

    float* new_nodes = (float*)d_out;
    float* messages  = (float*)d_out + (size_t)N_ * D;

    cudaFuncSetAttribute(node_proj_kernel,
                         cudaFuncAttributeMaxDynamicSharedMemorySize, NP_TOTAL);
    cudaFuncSetAttribute(edge_mma_kernel,
                         cudaFuncAttributeMaxDynamicSharedMemorySize, EG_TOTAL);
    cudaFuncSetAttribute(gru_mma_kernel,
                         cudaFuncAttributeMaxDynamicSharedMemorySize, GR_TOTAL);

    const int ntiles = (E_ + 127) / 128;
    const int egrid  = ntiles < 148 ? ntiles : 148;

    // CSR build must precede the edge kernel (elist ordering)
    prep_kernel<<<96, 256>>>(W_edge, Wi, Wh, N_);
    hist_kernel<<<(E_ + 255) / 256, 256>>>(rcv, E_);
    scan_kernel<<<1, 1024>>>(N_, E_);
    scatter_kernel<<<(E_ + 255) / 256, 256>>>(rcv, E_);
    node_proj_kernel<<<(N_ + 255) / 256, 512, NP_TOTAL>>>(nodes, N_);
    edge_mma_kernel<<<egrid, 512, EG_TOTAL>>>(
        edges, b_edge, snd, rcv, messages, E_, ntiles);
    aggregate_kernel<<<N_, 128>>>(messages, N_);
    gru_mma_kernel<<<(N_ + 127) / 128, 256, GR_TOTAL>>>(nodes, N_);
    gru_elem_kernel<<<(N_ * D + 255) / 256, 256>>>(nodes, bi, bh_n,
                                                   new_nodes, N_ * D);
}